// round 2
// baseline (speedup 1.0000x reference)
#include <cuda_runtime.h>
#include <math.h>

// ---------------- problem constants ----------------
#define DIMC   384
#define NPIX   4096
#define BATCH  16
#define HEADS  4
#define CH     96
#define QKVROWS 1152
#define QSCALE 0.1020620726159658f   // 96^-0.5

// ---------------- scratch (device globals; allocation-free contract) ----------------
__device__ float g_Wg[QKVROWS * DIMC];
__device__ float g_wsum[QKVROWS];
__device__ float g_mean[BATCH * NPIX];
__device__ float g_rstd[BATCH * NPIX];
__device__ float g_mean2[BATCH * NPIX];
__device__ float g_rstd2[BATCH * NPIX];
__device__ float g_qkv[(size_t)BATCH * QKVROWS * NPIX];     // 302 MB
__device__ float g_ctxT[BATCH * HEADS * CH * CH];           // ctx^T: [bh][e][d]
__device__ float g_attn[(size_t)BATCH * DIMC * NPIX];       // 100 MB
__device__ float g_y[(size_t)BATCH * DIMC * NPIX];          // 100 MB

// ---------------- prep: W' = Wqkv * prenorm_g, row sums ----------------
__global__ void prep_w_kernel(const float* __restrict__ W, const float* __restrict__ g)
{
    int warp = (blockIdx.x * blockDim.x + threadIdx.x) >> 5;
    int lane = threadIdx.x & 31;
    if (warp >= QKVROWS) return;
    float s = 0.f;
    for (int c = lane; c < DIMC; c += 32) {
        float w = W[warp * DIMC + c] * g[c];
        g_Wg[warp * DIMC + c] = w;
        s += w;
    }
    #pragma unroll
    for (int o = 16; o > 0; o >>= 1) s += __shfl_down_sync(0xffffffffu, s, o);
    if (lane == 0) g_wsum[warp] = s;
}

// ---------------- channel-LN statistics (mean / rstd over C=384) ----------------
// MODE 0: src = x (arg). MODE 1: src = g_y.  dst selected by MODE.
template<int MODE>
__global__ void chan_stats_kernel(const float* __restrict__ xarg)
{
    int p = blockIdx.x * blockDim.x + threadIdx.x;     // b*4096 + pix
    if (p >= BATCH * NPIX) return;
    const float* src = (MODE == 0) ? xarg : g_y;
    const float* base = src + (size_t)(p >> 12) * DIMC * NPIX + (p & (NPIX - 1));
    float s = 0.f, s2 = 0.f;
    #pragma unroll 4
    for (int c = 0; c < DIMC; c++) {
        float v = base[(size_t)c * NPIX];
        s += v; s2 += v * v;
    }
    float m   = s * (1.f / DIMC);
    float var = s2 * (1.f / DIMC) - m * m;
    float r   = rsqrtf(var + 1e-5f);
    if (MODE == 0) { g_mean[p]  = m; g_rstd[p]  = r; }
    else           { g_mean2[p] = m; g_rstd2[p] = r; }
}

// ---------------- tiled SGEMM, 128x128x16, 256 thr, 8x8/thread ----------------
// KIND 0: qkv = rstd*(Wg@x - mean*wsum)        A=g_Wg      B=x(arg)   C=g_qkv
// KIND 1: y   = Wout@attn + bout               A=Wout(arg) B=g_attn   C=g_y
// KIND 2: attn= ctxT@q (per b,h)               A=g_ctxT    B=g_qkv    C=g_attn
#define BM 128
#define BN 128
#define BK 16

template<int KIND, int M, int K>
__global__ __launch_bounds__(256)
void sgemm_kernel(const float* __restrict__ Aext, const float* __restrict__ Bext,
                  const float* __restrict__ bias)
{
    const int N = NPIX;
    __shared__ float As[BK][BM];
    __shared__ float Bs[BK][BN];

    int z = blockIdx.z;
    const float* A; const float* B; float* C;
    const float* mean = nullptr; const float* rstd = nullptr;

    if (KIND == 0) {
        A = g_Wg;
        B = Bext + (size_t)z * K * N;
        C = g_qkv + (size_t)z * M * N;
        mean = g_mean + (size_t)z * N;
        rstd = g_rstd + (size_t)z * N;
    } else if (KIND == 1) {
        A = Aext;
        B = g_attn + (size_t)z * K * N;
        C = g_y + (size_t)z * M * N;
    } else { // KIND == 2
        int b = z >> 2, h = z & 3;
        A = g_ctxT + (size_t)z * CH * CH;
        B = g_qkv + ((size_t)b * QKVROWS + h * CH) * N;   // q region
        C = g_attn + ((size_t)b * DIMC + h * CH) * N;
    }

    int tid = threadIdx.x;
    int tx = tid & 15, ty = tid >> 4;
    int rowBase = blockIdx.y * BM;
    int colBase = blockIdx.x * BN;

    float acc[8][8];
    #pragma unroll
    for (int i = 0; i < 8; i++)
        #pragma unroll
        for (int j = 0; j < 8; j++) acc[i][j] = 0.f;

    for (int k0 = 0; k0 < K; k0 += BK) {
        #pragma unroll
        for (int i = 0; i < 2; i++) {
            int idx = tid + i * 256;          // 0..511 float4
            int r   = idx >> 2;               // 0..127
            int c4  = (idx & 3) << 2;         // 0,4,8,12
            float4 a;
            int gr = rowBase + r;
            if (gr < M) a = *(const float4*)&A[(size_t)gr * K + k0 + c4];
            else        a = make_float4(0.f, 0.f, 0.f, 0.f);
            As[c4 + 0][r] = a.x; As[c4 + 1][r] = a.y;
            As[c4 + 2][r] = a.z; As[c4 + 3][r] = a.w;
        }
        #pragma unroll
        for (int i = 0; i < 2; i++) {
            int idx = tid + i * 256;
            int r   = idx >> 5;               // 0..15
            int c4  = (idx & 31) << 2;        // 0..124
            *(float4*)&Bs[r][c4] = *(const float4*)&B[(size_t)(k0 + r) * N + colBase + c4];
        }
        __syncthreads();

        #pragma unroll
        for (int kk = 0; kk < BK; kk++) {
            float4 a0 = *(const float4*)&As[kk][ty * 8];
            float4 a1 = *(const float4*)&As[kk][ty * 8 + 4];
            float4 b0 = *(const float4*)&Bs[kk][tx * 8];
            float4 b1 = *(const float4*)&Bs[kk][tx * 8 + 4];
            float ar[8] = {a0.x, a0.y, a0.z, a0.w, a1.x, a1.y, a1.z, a1.w};
            float br[8] = {b0.x, b0.y, b0.z, b0.w, b1.x, b1.y, b1.z, b1.w};
            #pragma unroll
            for (int i = 0; i < 8; i++)
                #pragma unroll
                for (int j = 0; j < 8; j++)
                    acc[i][j] += ar[i] * br[j];
        }
        __syncthreads();
    }

    if (KIND == 0) {
        float mv[8], rv[8];
        #pragma unroll
        for (int j = 0; j < 8; j++) {
            int gc = colBase + tx * 8 + j;
            mv[j] = mean[gc]; rv[j] = rstd[gc];
        }
        #pragma unroll
        for (int i = 0; i < 8; i++) {
            int gr = rowBase + ty * 8 + i;
            float ws = g_wsum[gr];
            #pragma unroll
            for (int j = 0; j < 8; j++) {
                int gc = colBase + tx * 8 + j;
                C[(size_t)gr * N + gc] = rv[j] * (acc[i][j] - mv[j] * ws);
            }
        }
    } else if (KIND == 1) {
        #pragma unroll
        for (int i = 0; i < 8; i++) {
            int gr = rowBase + ty * 8 + i;
            float bb = bias[gr];
            #pragma unroll
            for (int j = 0; j < 8; j++) {
                int gc = colBase + tx * 8 + j;
                C[(size_t)gr * N + gc] = acc[i][j] + bb;
            }
        }
    } else {
        #pragma unroll
        for (int i = 0; i < 8; i++) {
            int gr = rowBase + ty * 8 + i;
            if (gr < M) {
                #pragma unroll
                for (int j = 0; j < 8; j++) {
                    int gc = colBase + tx * 8 + j;
                    C[(size_t)gr * N + gc] = acc[i][j];
                }
            }
        }
    }
}

// ---------------- q softmax over channel dim (96) per (b,h,pixel) ----------------
__global__ __launch_bounds__(128) void q_softmax_kernel()
{
    int idx = blockIdx.x * blockDim.x + threadIdx.x;
    if (idx >= BATCH * HEADS * NPIX) return;
    int pix = idx & 4095;
    int h   = (idx >> 12) & 3;
    int b   = idx >> 14;
    float* base = g_qkv + ((size_t)b * QKVROWS + h * CH) * NPIX + pix;

    float v[CH];
    float mx = -1e30f;
    #pragma unroll
    for (int d = 0; d < CH; d++) {
        v[d] = base[(size_t)d * NPIX];
        mx = fmaxf(mx, v[d]);
    }
    float s = 0.f;
    #pragma unroll
    for (int d = 0; d < CH; d++) {
        v[d] = __expf(v[d] - mx);
        s += v[d];
    }
    float inv = QSCALE / s;
    #pragma unroll
    for (int d = 0; d < CH; d++) base[(size_t)d * NPIX] = v[d] * inv;
}

// ---------------- k softmax over spatial dim (4096) per (b, channel) ----------------
__global__ __launch_bounds__(256) void k_softmax_kernel()
{
    int row = blockIdx.x;                 // 0..6143
    int b = row / DIMC, r = row % DIMC;
    float* base = g_qkv + ((size_t)b * QKVROWS + DIMC + r) * NPIX;
    int tid  = threadIdx.x;
    int lane = tid & 31, warp = tid >> 5;

    float4 v[4];
    float mx = -1e30f;
    #pragma unroll
    for (int j = 0; j < 4; j++) {
        v[j] = *(const float4*)&base[(j * 256 + tid) * 4];
        mx = fmaxf(mx, fmaxf(fmaxf(v[j].x, v[j].y), fmaxf(v[j].z, v[j].w)));
    }
    __shared__ float smax[8];
    __shared__ float ssum[8];
    #pragma unroll
    for (int o = 16; o > 0; o >>= 1) mx = fmaxf(mx, __shfl_xor_sync(0xffffffffu, mx, o));
    if (lane == 0) smax[warp] = mx;
    __syncthreads();
    mx = smax[0];
    #pragma unroll
    for (int w = 1; w < 8; w++) mx = fmaxf(mx, smax[w]);

    float s = 0.f;
    #pragma unroll
    for (int j = 0; j < 4; j++) {
        v[j].x = __expf(v[j].x - mx); v[j].y = __expf(v[j].y - mx);
        v[j].z = __expf(v[j].z - mx); v[j].w = __expf(v[j].w - mx);
        s += v[j].x + v[j].y + v[j].z + v[j].w;
    }
    #pragma unroll
    for (int o = 16; o > 0; o >>= 1) s += __shfl_xor_sync(0xffffffffu, s, o);
    if (lane == 0) ssum[warp] = s;
    __syncthreads();
    s = 0.f;
    #pragma unroll
    for (int w = 0; w < 8; w++) s += ssum[w];

    float inv = 1.f / s;
    #pragma unroll
    for (int j = 0; j < 4; j++) {
        v[j].x *= inv; v[j].y *= inv; v[j].z *= inv; v[j].w *= inv;
        *(float4*)&base[(j * 256 + tid) * 4] = v[j];
    }
}

// ---------------- zero ctx accumulator ----------------
__global__ void zero_ctx_kernel()
{
    int i = blockIdx.x * blockDim.x + threadIdx.x;
    if (i < BATCH * HEADS * CH * CH) g_ctxT[i] = 0.f;
}

// ---------------- ctxT[e][d] = sum_n v[e,n] * k[d,n], split-K=8 ----------------
__global__ __launch_bounds__(256) void ctx_kernel()
{
    int sk = blockIdx.x;                  // 0..7, K-slice of 512
    int bh = blockIdx.y;                  // 0..63
    int b = bh >> 2, h = bh & 3;
    const float* kb = g_qkv + ((size_t)b * QKVROWS + DIMC     + h * CH) * NPIX;
    const float* vb = g_qkv + ((size_t)b * QKVROWS + 2 * DIMC + h * CH) * NPIX;

    __shared__ float ks[32][CH + 1];
    __shared__ float vs[32][CH + 1];
    int tid = threadIdx.x;
    int tx = tid & 15, ty = tid >> 4;
    float acc[6][6];
    #pragma unroll
    for (int i = 0; i < 6; i++)
        #pragma unroll
        for (int j = 0; j < 6; j++) acc[i][j] = 0.f;

    int n0 = sk * 512;
    for (int nt = 0; nt < 512; nt += 32) {
        #pragma unroll
        for (int i = 0; i < 12; i++) {
            int idx = tid + i * 256;       // 0..3071
            int d  = idx >> 5;             // 0..95
            int nn = idx & 31;
            ks[nn][d] = kb[(size_t)d * NPIX + n0 + nt + nn];
            vs[nn][d] = vb[(size_t)d * NPIX + n0 + nt + nn];
        }
        __syncthreads();
        #pragma unroll
        for (int nn = 0; nn < 32; nn++) {
            float ar[6], br[6];
            #pragma unroll
            for (int i = 0; i < 6; i++) ar[i] = ks[nn][ty * 6 + i];
            #pragma unroll
            for (int j = 0; j < 6; j++) br[j] = vs[nn][tx * 6 + j];
            #pragma unroll
            for (int i = 0; i < 6; i++)
                #pragma unroll
                for (int j = 0; j < 6; j++) acc[i][j] += ar[i] * br[j];
        }
        __syncthreads();
    }

    float* cb = g_ctxT + (size_t)bh * CH * CH;
    #pragma unroll
    for (int i = 0; i < 6; i++) {
        int d = ty * 6 + i;
        #pragma unroll
        for (int j = 0; j < 6; j++) {
            int e = tx * 6 + j;
            atomicAdd(&cb[e * CH + d], acc[i][j]);
        }
    }
}

// ---------------- final: LN(y)*outg + (x-mean)*rstd*preg ----------------
__global__ void final_kernel(const float* __restrict__ x, const float* __restrict__ preg,
                             const float* __restrict__ outg, float* __restrict__ out)
{
    size_t i = (size_t)blockIdx.x * blockDim.x + threadIdx.x;
    if (i >= (size_t)BATCH * DIMC * NPIX) return;
    int pix = (int)(i & 4095);
    int bc  = (int)(i >> 12);             // b*384 + c
    int c   = bc % DIMC;
    int b   = bc / DIMC;
    int bp  = b * NPIX + pix;
    float xn = (x[i]   - g_mean[bp])  * g_rstd[bp]  * preg[c];
    float yn = (g_y[i] - g_mean2[bp]) * g_rstd2[bp] * outg[c];
    out[i] = yn + xn;
}

// ---------------- launch ----------------
extern "C" void kernel_launch(void* const* d_in, const int* in_sizes, int n_in,
                              void* d_out, int out_size)
{
    const float* x    = (const float*)d_in[0];
    const float* preg = (const float*)d_in[1];
    const float* Wqkv = (const float*)d_in[2];
    const float* Wout = (const float*)d_in[3];
    const float* bout = (const float*)d_in[4];
    const float* outg = (const float*)d_in[5];
    float* out = (float*)d_out;
    (void)in_sizes; (void)n_in; (void)out_size;

    // 1. prep folded weights + prenorm stats
    prep_w_kernel<<<(QKVROWS * 32 + 255) / 256, 256>>>(Wqkv, preg);
    chan_stats_kernel<0><<<(BATCH * NPIX) / 256, 256>>>(x);

    // 2. QKV GEMM with LN folded into the epilogue
    sgemm_kernel<0, QKVROWS, DIMC><<<dim3(NPIX / BN, QKVROWS / BM, BATCH), 256>>>(nullptr, x, nullptr);

    // 3. softmaxes (in place in g_qkv)
    q_softmax_kernel<<<(BATCH * HEADS * NPIX) / 128, 128>>>();
    k_softmax_kernel<<<BATCH * DIMC, 256>>>();

    // 4. context (split-K via atomics) and apply to q
    zero_ctx_kernel<<<(BATCH * HEADS * CH * CH + 255) / 256, 256>>>();
    ctx_kernel<<<dim3(8, BATCH * HEADS), 256>>>();
    sgemm_kernel<2, CH, CH><<<dim3(NPIX / BN, 1, BATCH * HEADS), 256>>>(nullptr, nullptr, nullptr);

    // 5. out projection + bias
    sgemm_kernel<1, DIMC, DIMC><<<dim3(NPIX / BN, DIMC / BM, BATCH), 256>>>(Wout, nullptr, bout);

    // 6. out-LN stats + fused LN/residual epilogue
    chan_stats_kernel<1><<<(BATCH * NPIX) / 256, 256>>>(nullptr);
    final_kernel<<<(int)(((size_t)BATCH * DIMC * NPIX + 255) / 256), 256>>>(x, preg, outg, out);
}

// round 4
// speedup vs baseline: 1.6626x; 1.6626x over previous
#include <cuda_runtime.h>
#include <math.h>

// ---------------- problem constants ----------------
#define DIMC   384
#define NPIX   4096
#define BATCH  16
#define HEADS  4
#define CH     96
#define QKVROWS 1152
#define QSCALE 0.1020620726159658f   // 96^-0.5

// ---------------- scratch (device globals; allocation-free contract) ----------------
__device__ float g_Wg[QKVROWS * DIMC];
__device__ float g_wsum[QKVROWS];
__device__ float g_mean[BATCH * NPIX];
__device__ float g_rstd[BATCH * NPIX];
__device__ float g_mean2[BATCH * NPIX];
__device__ float g_rstd2[BATCH * NPIX];
__device__ float g_qkv[(size_t)BATCH * QKVROWS * NPIX];     // 302 MB
__device__ float g_ctxT[BATCH * HEADS * CH * CH];           // ctx^T: [bh][e][d]
__device__ float g_attn[(size_t)BATCH * DIMC * NPIX];       // 100 MB
__device__ float g_y[(size_t)BATCH * DIMC * NPIX];          // 100 MB

// ---------------- helpers ----------------
__device__ __forceinline__ unsigned f2tf_u(float f) {
    unsigned u;
    asm("cvt.rna.tf32.f32 %0, %1;" : "=r"(u) : "f"(f));
    return u;
}
__device__ __forceinline__ float f2tf(float f) {
    return __uint_as_float(f2tf_u(f));   // tf32-rounded value, valid fp32
}

// ---------------- prep: W' = tf32(Wqkv * prenorm_g), row sums over rounded ----------------
__global__ void prep_w_kernel(const float* __restrict__ W, const float* __restrict__ g)
{
    int warp = (blockIdx.x * blockDim.x + threadIdx.x) >> 5;
    int lane = threadIdx.x & 31;
    if (warp >= QKVROWS) return;
    float s = 0.f;
    for (int c = lane; c < DIMC; c += 32) {
        float w = f2tf(W[warp * DIMC + c] * g[c]);
        g_Wg[warp * DIMC + c] = w;
        s += w;
    }
    #pragma unroll
    for (int o = 16; o > 0; o >>= 1) s += __shfl_down_sync(0xffffffffu, s, o);
    if (lane == 0) g_wsum[warp] = s;
}

// ---------------- channel-LN statistics (mean / rstd over C=384) ----------------
template<int MODE>
__global__ void chan_stats_kernel(const float* __restrict__ xarg)
{
    int p = blockIdx.x * blockDim.x + threadIdx.x;     // b*4096 + pix
    if (p >= BATCH * NPIX) return;
    const float* src = (MODE == 0) ? xarg : g_y;
    const float* base = src + (size_t)(p >> 12) * DIMC * NPIX + (p & (NPIX - 1));
    float s = 0.f, s2 = 0.f;
    #pragma unroll 4
    for (int c = 0; c < DIMC; c++) {
        float v = base[(size_t)c * NPIX];
        s += v; s2 += v * v;
    }
    float m   = s * (1.f / DIMC);
    float var = s2 * (1.f / DIMC) - m * m;
    float r   = rsqrtf(var + 1e-5f);
    if (MODE == 0) { g_mean[p]  = m; g_rstd[p]  = r; }
    else           { g_mean2[p] = m; g_rstd2[p] = r; }
}

// =======================================================================
// tf32 tensor-core GEMM: 128x128x16, 256 thr (8 warps, 4x2), warp 32x64
// mma.sync.aligned.m16n8k8.row.col.f32.tf32.tf32.f32
// KIND 0: qkv = rstd*(Wg@x - mean*wsum)     A=g_Wg      B=x(arg)   C=g_qkv
// KIND 1: y   = Wout@attn + bout            A=Wout(arg) B=g_attn   C=g_y
// =======================================================================
#define BM 128
#define BN 128
#define BK 16
#define LDA (BM + 4)
#define LDB (BN + 4)

template<int KIND, int M, int K>
__global__ __launch_bounds__(256, 2)
void tf32gemm_kernel(const float* __restrict__ Aext, const float* __restrict__ Bext,
                     const float* __restrict__ bias)
{
    const int N = NPIX;
    __shared__ float As[BK][LDA];
    __shared__ float Bs[BK][LDB];

    int z = blockIdx.z;
    const float* A; const float* B; float* C;
    const float* mean = nullptr; const float* rstd = nullptr;

    if (KIND == 0) {
        A = g_Wg;
        B = Bext + (size_t)z * K * N;
        C = g_qkv + (size_t)z * M * N;
        mean = g_mean + (size_t)z * N;
        rstd = g_rstd + (size_t)z * N;
    } else {
        A = Aext;
        B = g_attn + (size_t)z * K * N;
        C = g_y + (size_t)z * M * N;
    }

    int tid  = threadIdx.x;
    int lane = tid & 31;
    int wid  = tid >> 5;
    int warpM = wid & 3;        // 0..3 -> 32-row slices
    int warpN = wid >> 2;       // 0..1 -> 64-col slices
    int gid = lane >> 2;        // 0..7
    int tig = lane & 3;         // 0..3

    int rowBase = blockIdx.y * BM;
    int colBase = blockIdx.x * BN;

    float acc[2][8][4];
    #pragma unroll
    for (int i = 0; i < 2; i++)
        #pragma unroll
        for (int j = 0; j < 8; j++)
            #pragma unroll
            for (int t = 0; t < 4; t++) acc[i][j][t] = 0.f;

    for (int k0 = 0; k0 < K; k0 += BK) {
        // A tile [BM x BK] -> As[k][m], tf32-rounded
        #pragma unroll
        for (int i = 0; i < 2; i++) {
            int idx = tid + i * 256;          // 0..511 float4
            int r   = idx >> 2;               // 0..127
            int c4  = (idx & 3) << 2;         // 0,4,8,12
            int gr  = rowBase + r;
            float4 a = (gr < M) ? *(const float4*)&A[(size_t)gr * K + k0 + c4]
                                : make_float4(0.f, 0.f, 0.f, 0.f);
            As[c4 + 0][r] = f2tf(a.x); As[c4 + 1][r] = f2tf(a.y);
            As[c4 + 2][r] = f2tf(a.z); As[c4 + 3][r] = f2tf(a.w);
        }
        // B tile [BK x BN] -> Bs[k][n], tf32-rounded
        #pragma unroll
        for (int i = 0; i < 2; i++) {
            int idx = tid + i * 256;
            int r   = idx >> 5;               // 0..15
            int c4  = (idx & 31) << 2;        // 0..124
            float4 b = *(const float4*)&B[(size_t)(k0 + r) * N + colBase + c4];
            Bs[r][c4 + 0] = f2tf(b.x); Bs[r][c4 + 1] = f2tf(b.y);
            Bs[r][c4 + 2] = f2tf(b.z); Bs[r][c4 + 3] = f2tf(b.w);
        }
        __syncthreads();

        #pragma unroll
        for (int ks = 0; ks < 2; ks++) {
            int kb = ks * 8;
            unsigned af[2][4];
            #pragma unroll
            for (int i = 0; i < 2; i++) {
                int mr = warpM * 32 + i * 16 + gid;
                af[i][0] = __float_as_uint(As[kb + tig    ][mr]);
                af[i][1] = __float_as_uint(As[kb + tig    ][mr + 8]);
                af[i][2] = __float_as_uint(As[kb + tig + 4][mr]);
                af[i][3] = __float_as_uint(As[kb + tig + 4][mr + 8]);
            }
            unsigned bf[8][2];
            #pragma unroll
            for (int j = 0; j < 8; j++) {
                int nc = warpN * 64 + j * 8 + gid;
                bf[j][0] = __float_as_uint(Bs[kb + tig    ][nc]);
                bf[j][1] = __float_as_uint(Bs[kb + tig + 4][nc]);
            }
            #pragma unroll
            for (int i = 0; i < 2; i++)
                #pragma unroll
                for (int j = 0; j < 8; j++) {
                    asm volatile(
                        "mma.sync.aligned.m16n8k8.row.col.f32.tf32.tf32.f32 "
                        "{%0,%1,%2,%3},{%4,%5,%6,%7},{%8,%9},{%0,%1,%2,%3};\n"
                        : "+f"(acc[i][j][0]), "+f"(acc[i][j][1]),
                          "+f"(acc[i][j][2]), "+f"(acc[i][j][3])
                        : "r"(af[i][0]), "r"(af[i][1]), "r"(af[i][2]), "r"(af[i][3]),
                          "r"(bf[j][0]), "r"(bf[j][1]));
                }
        }
        __syncthreads();
    }

    // ---------------- epilogue ----------------
    #pragma unroll
    for (int i = 0; i < 2; i++) {
        int r0 = rowBase + warpM * 32 + i * 16 + gid;
        int r1 = r0 + 8;
        float w0 = 0.f, w1 = 0.f, bb0 = 0.f, bb1 = 0.f;
        if (KIND == 0) { w0 = g_wsum[r0]; w1 = g_wsum[r1]; }
        else           { bb0 = bias[r0];  bb1 = bias[r1]; }
        #pragma unroll
        for (int j = 0; j < 8; j++) {
            int c0 = colBase + warpN * 64 + j * 8 + 2 * tig;
            if (KIND == 0) {
                float m0 = mean[c0], m1 = mean[c0 + 1];
                float v0 = rstd[c0], v1 = rstd[c0 + 1];
                float2 o0 = make_float2(v0 * (acc[i][j][0] - m0 * w0),
                                        v1 * (acc[i][j][1] - m1 * w0));
                float2 o1 = make_float2(v0 * (acc[i][j][2] - m0 * w1),
                                        v1 * (acc[i][j][3] - m1 * w1));
                *(float2*)&C[(size_t)r0 * N + c0] = o0;
                *(float2*)&C[(size_t)r1 * N + c0] = o1;
            } else {
                float2 o0 = make_float2(acc[i][j][0] + bb0, acc[i][j][1] + bb0);
                float2 o1 = make_float2(acc[i][j][2] + bb1, acc[i][j][3] + bb1);
                *(float2*)&C[(size_t)r0 * N + c0] = o0;
                *(float2*)&C[(size_t)r1 * N + c0] = o1;
            }
        }
    }
}

// ---------------- FFMA sgemm kept for KIND 2 (attn apply, small) ----------------
template<int KIND, int M, int K>
__global__ __launch_bounds__(256)
void sgemm_kernel(const float* __restrict__ Aext, const float* __restrict__ Bext,
                  const float* __restrict__ bias)
{
    const int N = NPIX;
    __shared__ float As[BK][BM];
    __shared__ float Bs[BK][BN];

    int z = blockIdx.z;
    int b = z >> 2, h = z & 3;
    const float* A = g_ctxT + (size_t)z * CH * CH;
    const float* B = g_qkv + ((size_t)b * QKVROWS + h * CH) * N;   // q region
    float* C = g_attn + ((size_t)b * DIMC + h * CH) * N;
    (void)Aext; (void)Bext; (void)bias;

    int tid = threadIdx.x;
    int tx = tid & 15, ty = tid >> 4;
    int rowBase = blockIdx.y * BM;
    int colBase = blockIdx.x * BN;

    float acc[8][8];
    #pragma unroll
    for (int i = 0; i < 8; i++)
        #pragma unroll
        for (int j = 0; j < 8; j++) acc[i][j] = 0.f;

    for (int k0 = 0; k0 < K; k0 += BK) {
        #pragma unroll
        for (int i = 0; i < 2; i++) {
            int idx = tid + i * 256;
            int r   = idx >> 2;
            int c4  = (idx & 3) << 2;
            float4 a;
            int gr = rowBase + r;
            if (gr < M) a = *(const float4*)&A[(size_t)gr * K + k0 + c4];
            else        a = make_float4(0.f, 0.f, 0.f, 0.f);
            As[c4 + 0][r] = a.x; As[c4 + 1][r] = a.y;
            As[c4 + 2][r] = a.z; As[c4 + 3][r] = a.w;
        }
        #pragma unroll
        for (int i = 0; i < 2; i++) {
            int idx = tid + i * 256;
            int r   = idx >> 5;
            int c4  = (idx & 31) << 2;
            *(float4*)&Bs[r][c4] = *(const float4*)&B[(size_t)(k0 + r) * N + colBase + c4];
        }
        __syncthreads();

        #pragma unroll
        for (int kk = 0; kk < BK; kk++) {
            float4 a0 = *(const float4*)&As[kk][ty * 8];
            float4 a1 = *(const float4*)&As[kk][ty * 8 + 4];
            float4 b0 = *(const float4*)&Bs[kk][tx * 8];
            float4 b1 = *(const float4*)&Bs[kk][tx * 8 + 4];
            float ar[8] = {a0.x, a0.y, a0.z, a0.w, a1.x, a1.y, a1.z, a1.w};
            float br[8] = {b0.x, b0.y, b0.z, b0.w, b1.x, b1.y, b1.z, b1.w};
            #pragma unroll
            for (int i = 0; i < 8; i++)
                #pragma unroll
                for (int j = 0; j < 8; j++)
                    acc[i][j] += ar[i] * br[j];
        }
        __syncthreads();
    }

    #pragma unroll
    for (int i = 0; i < 8; i++) {
        int gr = rowBase + ty * 8 + i;
        if (gr < M) {
            #pragma unroll
            for (int j = 0; j < 8; j++) {
                int gc = colBase + tx * 8 + j;
                C[(size_t)gr * N + gc] = acc[i][j];
            }
        }
    }
}

// ---------------- q softmax over channel dim (96) per (b,h,pixel) ----------------
__global__ __launch_bounds__(128) void q_softmax_kernel()
{
    int idx = blockIdx.x * blockDim.x + threadIdx.x;
    if (idx >= BATCH * HEADS * NPIX) return;
    int pix = idx & 4095;
    int h   = (idx >> 12) & 3;
    int b   = idx >> 14;
    float* base = g_qkv + ((size_t)b * QKVROWS + h * CH) * NPIX + pix;

    float v[CH];
    float mx = -1e30f;
    #pragma unroll
    for (int d = 0; d < CH; d++) {
        v[d] = base[(size_t)d * NPIX];
        mx = fmaxf(mx, v[d]);
    }
    float s = 0.f;
    #pragma unroll
    for (int d = 0; d < CH; d++) {
        v[d] = __expf(v[d] - mx);
        s += v[d];
    }
    float inv = QSCALE / s;
    #pragma unroll
    for (int d = 0; d < CH; d++) base[(size_t)d * NPIX] = v[d] * inv;
}

// ---------------- k softmax over spatial dim (4096) per (b, channel) ----------------
__global__ __launch_bounds__(256) void k_softmax_kernel()
{
    int row = blockIdx.x;                 // 0..6143
    int b = row / DIMC, r = row % DIMC;
    float* base = g_qkv + ((size_t)b * QKVROWS + DIMC + r) * NPIX;
    int tid  = threadIdx.x;
    int lane = tid & 31, warp = tid >> 5;

    float4 v[4];
    float mx = -1e30f;
    #pragma unroll
    for (int j = 0; j < 4; j++) {
        v[j] = *(const float4*)&base[(j * 256 + tid) * 4];
        mx = fmaxf(mx, fmaxf(fmaxf(v[j].x, v[j].y), fmaxf(v[j].z, v[j].w)));
    }
    __shared__ float smax[8];
    __shared__ float ssum[8];
    #pragma unroll
    for (int o = 16; o > 0; o >>= 1) mx = fmaxf(mx, __shfl_xor_sync(0xffffffffu, mx, o));
    if (lane == 0) smax[warp] = mx;
    __syncthreads();
    mx = smax[0];
    #pragma unroll
    for (int w = 1; w < 8; w++) mx = fmaxf(mx, smax[w]);

    float s = 0.f;
    #pragma unroll
    for (int j = 0; j < 4; j++) {
        v[j].x = __expf(v[j].x - mx); v[j].y = __expf(v[j].y - mx);
        v[j].z = __expf(v[j].z - mx); v[j].w = __expf(v[j].w - mx);
        s += v[j].x + v[j].y + v[j].z + v[j].w;
    }
    #pragma unroll
    for (int o = 16; o > 0; o >>= 1) s += __shfl_xor_sync(0xffffffffu, s, o);
    if (lane == 0) ssum[warp] = s;
    __syncthreads();
    s = 0.f;
    #pragma unroll
    for (int w = 0; w < 8; w++) s += ssum[w];

    float inv = 1.f / s;
    #pragma unroll
    for (int j = 0; j < 4; j++) {
        v[j].x *= inv; v[j].y *= inv; v[j].z *= inv; v[j].w *= inv;
        *(float4*)&base[(j * 256 + tid) * 4] = v[j];
    }
}

// ---------------- zero ctx accumulator ----------------
__global__ void zero_ctx_kernel()
{
    int i = blockIdx.x * blockDim.x + threadIdx.x;
    if (i < BATCH * HEADS * CH * CH) g_ctxT[i] = 0.f;
}

// ---------------- ctxT[e][d] = sum_n v[e,n] * k[d,n], split-K=8 ----------------
__global__ __launch_bounds__(256) void ctx_kernel()
{
    int sk = blockIdx.x;                  // 0..7, K-slice of 512
    int bh = blockIdx.y;                  // 0..63
    int b = bh >> 2, h = bh & 3;
    const float* kb = g_qkv + ((size_t)b * QKVROWS + DIMC     + h * CH) * NPIX;
    const float* vb = g_qkv + ((size_t)b * QKVROWS + 2 * DIMC + h * CH) * NPIX;

    __shared__ float ks[32][CH + 1];
    __shared__ float vs[32][CH + 1];
    int tid = threadIdx.x;
    int tx = tid & 15, ty = tid >> 4;
    float acc[6][6];
    #pragma unroll
    for (int i = 0; i < 6; i++)
        #pragma unroll
        for (int j = 0; j < 6; j++) acc[i][j] = 0.f;

    int n0 = sk * 512;
    for (int nt = 0; nt < 512; nt += 32) {
        #pragma unroll
        for (int i = 0; i < 12; i++) {
            int idx = tid + i * 256;       // 0..3071
            int d  = idx >> 5;             // 0..95
            int nn = idx & 31;
            ks[nn][d] = kb[(size_t)d * NPIX + n0 + nt + nn];
            vs[nn][d] = vb[(size_t)d * NPIX + n0 + nt + nn];
        }
        __syncthreads();
        #pragma unroll
        for (int nn = 0; nn < 32; nn++) {
            float ar[6], br[6];
            #pragma unroll
            for (int i = 0; i < 6; i++) ar[i] = ks[nn][ty * 6 + i];
            #pragma unroll
            for (int j = 0; j < 6; j++) br[j] = vs[nn][tx * 6 + j];
            #pragma unroll
            for (int i = 0; i < 6; i++)
                #pragma unroll
                for (int j = 0; j < 6; j++) acc[i][j] += ar[i] * br[j];
        }
        __syncthreads();
    }

    float* cb = g_ctxT + (size_t)bh * CH * CH;
    #pragma unroll
    for (int i = 0; i < 6; i++) {
        int d = ty * 6 + i;
        #pragma unroll
        for (int j = 0; j < 6; j++) {
            int e = tx * 6 + j;
            atomicAdd(&cb[e * CH + d], acc[i][j]);
        }
    }
}

// ---------------- final: LN(y)*outg + (x-mean)*rstd*preg ----------------
__global__ void final_kernel(const float* __restrict__ x, const float* __restrict__ preg,
                             const float* __restrict__ outg, float* __restrict__ out)
{
    size_t i = (size_t)blockIdx.x * blockDim.x + threadIdx.x;
    if (i >= (size_t)BATCH * DIMC * NPIX) return;
    int pix = (int)(i & 4095);
    int bc  = (int)(i >> 12);             // b*384 + c
    int c   = bc % DIMC;
    int b   = bc / DIMC;
    int bp  = b * NPIX + pix;
    float xn = (x[i]   - g_mean[bp])  * g_rstd[bp]  * preg[c];
    float yn = (g_y[i] - g_mean2[bp]) * g_rstd2[bp] * outg[c];
    out[i] = yn + xn;
}

// ---------------- launch ----------------
extern "C" void kernel_launch(void* const* d_in, const int* in_sizes, int n_in,
                              void* d_out, int out_size)
{
    const float* x    = (const float*)d_in[0];
    const float* preg = (const float*)d_in[1];
    const float* Wqkv = (const float*)d_in[2];
    const float* Wout = (const float*)d_in[3];
    const float* bout = (const float*)d_in[4];
    const float* outg = (const float*)d_in[5];
    float* out = (float*)d_out;
    (void)in_sizes; (void)n_in; (void)out_size;

    // 1. prep folded (tf32-rounded) weights + prenorm stats
    prep_w_kernel<<<(QKVROWS * 32 + 255) / 256, 256>>>(Wqkv, preg);
    chan_stats_kernel<0><<<(BATCH * NPIX) / 256, 256>>>(x);

    // 2. QKV GEMM (tf32 tensor cores) with LN folded into epilogue
    tf32gemm_kernel<0, QKVROWS, DIMC><<<dim3(NPIX / BN, QKVROWS / BM, BATCH), 256>>>(nullptr, x, nullptr);

    // 3. softmaxes (in place in g_qkv)
    q_softmax_kernel<<<(BATCH * HEADS * NPIX) / 128, 128>>>();
    k_softmax_kernel<<<BATCH * DIMC, 256>>>();

    // 4. context (split-K via atomics) and apply to q
    zero_ctx_kernel<<<(BATCH * HEADS * CH * CH + 255) / 256, 256>>>();
    ctx_kernel<<<dim3(8, BATCH * HEADS), 256>>>();
    sgemm_kernel<2, CH, CH><<<dim3(NPIX / BN, 1, BATCH * HEADS), 256>>>(nullptr, nullptr, nullptr);

    // 5. out projection + bias (tf32 tensor cores)
    tf32gemm_kernel<1, DIMC, DIMC><<<dim3(NPIX / BN, DIMC / BM, BATCH), 256>>>(Wout, nullptr, bout);

    // 6. out-LN stats + fused LN/residual epilogue
    chan_stats_kernel<1><<<(BATCH * NPIX) / 256, 256>>>(nullptr);
    final_kernel<<<(int)(((size_t)BATCH * DIMC * NPIX + 255) / 256), 256>>>(x, preg, outg, out);
}

// round 5
// speedup vs baseline: 2.1742x; 1.3077x over previous
#include <cuda_runtime.h>
#include <math.h>

// ---------------- problem constants ----------------
#define DIMC   384
#define NPIX   4096
#define BATCH  16
#define HEADS  4
#define CH     96
#define QKVROWS 1152
#define QSCALE 0.1020620726159658f   // 96^-0.5
#define CTX_SPLIT 8

// ---------------- scratch (device globals; allocation-free contract) ----------------
__device__ float g_Wg[QKVROWS * DIMC];
__device__ float g_wsum[QKVROWS];
__device__ float g_mean[BATCH * NPIX];
__device__ float g_rstd[BATCH * NPIX];
__device__ float g_mean2[BATCH * NPIX];
__device__ float g_rstd2[BATCH * NPIX];
__device__ float g_qkv[(size_t)BATCH * QKVROWS * NPIX];     // 302 MB
__device__ float g_ctxT[BATCH * HEADS * CH * CH];           // ctx^T: [bh][e][d]
__device__ float g_attn[(size_t)BATCH * DIMC * NPIX];       // 100 MB
__device__ float g_y[(size_t)BATCH * DIMC * NPIX];          // 100 MB

// ---------------- helpers ----------------
__device__ __forceinline__ unsigned f2tf_u(float f) {
    unsigned u;
    asm("cvt.rna.tf32.f32 %0, %1;" : "=r"(u) : "f"(f));
    return u;
}
__device__ __forceinline__ float f2tf(float f) {
    return __uint_as_float(f2tf_u(f));
}

// ---------------- prep: W' = tf32(Wqkv * prenorm_g), row sums ----------------
__global__ void prep_w_kernel(const float* __restrict__ W, const float* __restrict__ g)
{
    int warp = (blockIdx.x * blockDim.x + threadIdx.x) >> 5;
    int lane = threadIdx.x & 31;
    if (warp >= QKVROWS) return;
    float s = 0.f;
    for (int c = lane; c < DIMC; c += 32) {
        float w = f2tf(W[warp * DIMC + c] * g[c]);
        g_Wg[warp * DIMC + c] = w;
        s += w;
    }
    #pragma unroll
    for (int o = 16; o > 0; o >>= 1) s += __shfl_down_sync(0xffffffffu, s, o);
    if (lane == 0) g_wsum[warp] = s;
}

// ---------------- channel-LN statistics over C=384 ----------------
template<int MODE>
__global__ void chan_stats_kernel(const float* __restrict__ xarg)
{
    int p = blockIdx.x * blockDim.x + threadIdx.x;
    if (p >= BATCH * NPIX) return;
    const float* src = (MODE == 0) ? xarg : g_y;
    const float* base = src + (size_t)(p >> 12) * DIMC * NPIX + (p & (NPIX - 1));
    float s = 0.f, s2 = 0.f;
    #pragma unroll 4
    for (int c = 0; c < DIMC; c++) {
        float v = base[(size_t)c * NPIX];
        s += v; s2 += v * v;
    }
    float m   = s * (1.f / DIMC);
    float var = s2 * (1.f / DIMC) - m * m;
    float r   = rsqrtf(var + 1e-5f);
    if (MODE == 0) { g_mean[p]  = m; g_rstd[p]  = r; }
    else           { g_mean2[p] = m; g_rstd2[p] = r; }
}

// =======================================================================
// tf32 tensor-core GEMM: 128x128x16, 256 thr (8 warps 4x2), warp 32x64
// register-staged software pipeline (prefetch next K-tile during MMA)
// KIND 0: qkv = rstd*(Wg@x - mean*wsum)     A=g_Wg      B=x(arg)   C=g_qkv
// KIND 1: y   = Wout@attn + bout            A=Wout(arg) B=g_attn   C=g_y
// KIND 2: attn= ctxT@q (per b,h; M=96,K=96) A=g_ctxT    B=q region C=g_attn
// =======================================================================
#define BM 128
#define BN 128
#define BK 16
#define LDA (BM + 4)
#define LDB (BN + 4)

template<int KIND, int M, int K>
__global__ __launch_bounds__(256, 2)
void tf32gemm_kernel(const float* __restrict__ Aext, const float* __restrict__ Bext,
                     const float* __restrict__ bias)
{
    const int N = NPIX;
    __shared__ float As[BK][LDA];
    __shared__ float Bs[BK][LDB];

    int z = blockIdx.z;
    const float* A; const float* B; float* C;
    const float* mean = nullptr; const float* rstd = nullptr;

    if (KIND == 0) {
        A = g_Wg;
        B = Bext + (size_t)z * K * N;
        C = g_qkv + (size_t)z * M * N;
        mean = g_mean + (size_t)z * N;
        rstd = g_rstd + (size_t)z * N;
    } else if (KIND == 1) {
        A = Aext;
        B = g_attn + (size_t)z * K * N;
        C = g_y + (size_t)z * M * N;
    } else { // KIND == 2: apply ctxT @ q
        int b = z >> 2, h = z & 3;
        A = g_ctxT + (size_t)z * CH * CH;
        B = g_qkv + ((size_t)b * QKVROWS + h * CH) * N;       // q region
        C = g_attn + ((size_t)b * DIMC + h * CH) * N;
    }

    int tid  = threadIdx.x;
    int lane = tid & 31;
    int wid  = tid >> 5;
    int warpM = wid & 3;        // 0..3 -> 32-row slices
    int warpN = wid >> 2;       // 0..1 -> 64-col slices
    int gid = lane >> 2;        // 0..7
    int tig = lane & 3;         // 0..3

    int rowBase = blockIdx.y * BM;
    int colBase = blockIdx.x * BN;

    float acc[2][8][4];
    #pragma unroll
    for (int i = 0; i < 2; i++)
        #pragma unroll
        for (int j = 0; j < 8; j++)
            #pragma unroll
            for (int t = 0; t < 4; t++) acc[i][j][t] = 0.f;

    float4 aReg[2], bReg[2];
    // prologue: stage K-tile 0 in registers
    #pragma unroll
    for (int i = 0; i < 2; i++) {
        int idx = tid + i * 256;
        int r   = idx >> 2;
        int c4  = (idx & 3) << 2;
        int gr  = rowBase + r;
        aReg[i] = (gr < M) ? *(const float4*)&A[(size_t)gr * K + c4]
                           : make_float4(0.f, 0.f, 0.f, 0.f);
        int rb  = idx >> 5;
        int cb4 = (idx & 31) << 2;
        bReg[i] = *(const float4*)&B[(size_t)rb * N + colBase + cb4];
    }

    for (int k0 = 0; k0 < K; k0 += BK) {
        // commit staged registers into smem (tf32-rounded)
        #pragma unroll
        for (int i = 0; i < 2; i++) {
            int idx = tid + i * 256;
            int r   = idx >> 2;
            int c4  = (idx & 3) << 2;
            As[c4 + 0][r] = f2tf(aReg[i].x); As[c4 + 1][r] = f2tf(aReg[i].y);
            As[c4 + 2][r] = f2tf(aReg[i].z); As[c4 + 3][r] = f2tf(aReg[i].w);
            int rb  = idx >> 5;
            int cb4 = (idx & 31) << 2;
            Bs[rb][cb4 + 0] = f2tf(bReg[i].x); Bs[rb][cb4 + 1] = f2tf(bReg[i].y);
            Bs[rb][cb4 + 2] = f2tf(bReg[i].z); Bs[rb][cb4 + 3] = f2tf(bReg[i].w);
        }
        __syncthreads();

        // prefetch next K-tile (latency overlapped with MMA below)
        int k1 = k0 + BK;
        if (k1 < K) {
            #pragma unroll
            for (int i = 0; i < 2; i++) {
                int idx = tid + i * 256;
                int r   = idx >> 2;
                int c4  = (idx & 3) << 2;
                int gr  = rowBase + r;
                aReg[i] = (gr < M) ? *(const float4*)&A[(size_t)gr * K + k1 + c4]
                                   : make_float4(0.f, 0.f, 0.f, 0.f);
                int rb  = idx >> 5;
                int cb4 = (idx & 31) << 2;
                bReg[i] = *(const float4*)&B[(size_t)(k1 + rb) * N + colBase + cb4];
            }
        }

        #pragma unroll
        for (int ks = 0; ks < 2; ks++) {
            int kb = ks * 8;
            unsigned af[2][4];
            #pragma unroll
            for (int i = 0; i < 2; i++) {
                int mr = warpM * 32 + i * 16 + gid;
                af[i][0] = __float_as_uint(As[kb + tig    ][mr]);
                af[i][1] = __float_as_uint(As[kb + tig    ][mr + 8]);
                af[i][2] = __float_as_uint(As[kb + tig + 4][mr]);
                af[i][3] = __float_as_uint(As[kb + tig + 4][mr + 8]);
            }
            unsigned bf[8][2];
            #pragma unroll
            for (int j = 0; j < 8; j++) {
                int nc = warpN * 64 + j * 8 + gid;
                bf[j][0] = __float_as_uint(Bs[kb + tig    ][nc]);
                bf[j][1] = __float_as_uint(Bs[kb + tig + 4][nc]);
            }
            #pragma unroll
            for (int i = 0; i < 2; i++)
                #pragma unroll
                for (int j = 0; j < 8; j++) {
                    asm volatile(
                        "mma.sync.aligned.m16n8k8.row.col.f32.tf32.tf32.f32 "
                        "{%0,%1,%2,%3},{%4,%5,%6,%7},{%8,%9},{%0,%1,%2,%3};\n"
                        : "+f"(acc[i][j][0]), "+f"(acc[i][j][1]),
                          "+f"(acc[i][j][2]), "+f"(acc[i][j][3])
                        : "r"(af[i][0]), "r"(af[i][1]), "r"(af[i][2]), "r"(af[i][3]),
                          "r"(bf[j][0]), "r"(bf[j][1]));
                }
        }
        __syncthreads();
    }

    // ---------------- epilogue ----------------
    #pragma unroll
    for (int i = 0; i < 2; i++) {
        int r0 = rowBase + warpM * 32 + i * 16 + gid;
        int r1 = r0 + 8;
        float w0 = 0.f, w1 = 0.f, bb0 = 0.f, bb1 = 0.f;
        if (KIND == 0)      { w0 = g_wsum[r0]; w1 = g_wsum[r1]; }
        else if (KIND == 1) { bb0 = bias[r0];  bb1 = bias[r1]; }
        #pragma unroll
        for (int j = 0; j < 8; j++) {
            int c0 = colBase + warpN * 64 + j * 8 + 2 * tig;
            if (KIND == 0) {
                float m0 = mean[c0], m1 = mean[c0 + 1];
                float v0 = rstd[c0], v1 = rstd[c0 + 1];
                float2 o0 = make_float2(v0 * (acc[i][j][0] - m0 * w0),
                                        v1 * (acc[i][j][1] - m1 * w0));
                float2 o1 = make_float2(v0 * (acc[i][j][2] - m0 * w1),
                                        v1 * (acc[i][j][3] - m1 * w1));
                *(float2*)&C[(size_t)r0 * N + c0] = o0;
                *(float2*)&C[(size_t)r1 * N + c0] = o1;
            } else if (KIND == 1) {
                float2 o0 = make_float2(acc[i][j][0] + bb0, acc[i][j][1] + bb0);
                float2 o1 = make_float2(acc[i][j][2] + bb1, acc[i][j][3] + bb1);
                *(float2*)&C[(size_t)r0 * N + c0] = o0;
                *(float2*)&C[(size_t)r1 * N + c0] = o1;
            } else {
                if (r0 < M)
                    *(float2*)&C[(size_t)r0 * N + c0] =
                        make_float2(acc[i][j][0], acc[i][j][1]);
                if (r1 < M)
                    *(float2*)&C[(size_t)r1 * N + c0] =
                        make_float2(acc[i][j][2], acc[i][j][3]);
            }
        }
    }
}

// ---------------- q softmax over channel dim (96) per (b,h,pixel) ----------------
__global__ __launch_bounds__(128) void q_softmax_kernel()
{
    int idx = blockIdx.x * blockDim.x + threadIdx.x;
    if (idx >= BATCH * HEADS * NPIX) return;
    int pix = idx & 4095;
    int h   = (idx >> 12) & 3;
    int b   = idx >> 14;
    float* base = g_qkv + ((size_t)b * QKVROWS + h * CH) * NPIX + pix;

    float v[CH];
    float mx = -1e30f;
    #pragma unroll
    for (int d = 0; d < CH; d++) {
        v[d] = base[(size_t)d * NPIX];
        mx = fmaxf(mx, v[d]);
    }
    float s = 0.f;
    #pragma unroll
    for (int d = 0; d < CH; d++) {
        v[d] = __expf(v[d] - mx);
        s += v[d];
    }
    float inv = QSCALE / s;
    #pragma unroll
    for (int d = 0; d < CH; d++) base[(size_t)d * NPIX] = v[d] * inv;
}

// ---------------- k softmax over spatial dim (4096) per (b, channel) ----------------
__global__ __launch_bounds__(256) void k_softmax_kernel()
{
    int row = blockIdx.x;
    int b = row / DIMC, r = row % DIMC;
    float* base = g_qkv + ((size_t)b * QKVROWS + DIMC + r) * NPIX;
    int tid  = threadIdx.x;
    int lane = tid & 31, warp = tid >> 5;

    float4 v[4];
    float mx = -1e30f;
    #pragma unroll
    for (int j = 0; j < 4; j++) {
        v[j] = *(const float4*)&base[(j * 256 + tid) * 4];
        mx = fmaxf(mx, fmaxf(fmaxf(v[j].x, v[j].y), fmaxf(v[j].z, v[j].w)));
    }
    __shared__ float smax[8];
    __shared__ float ssum[8];
    #pragma unroll
    for (int o = 16; o > 0; o >>= 1) mx = fmaxf(mx, __shfl_xor_sync(0xffffffffu, mx, o));
    if (lane == 0) smax[warp] = mx;
    __syncthreads();
    mx = smax[0];
    #pragma unroll
    for (int w = 1; w < 8; w++) mx = fmaxf(mx, smax[w]);

    float s = 0.f;
    #pragma unroll
    for (int j = 0; j < 4; j++) {
        v[j].x = __expf(v[j].x - mx); v[j].y = __expf(v[j].y - mx);
        v[j].z = __expf(v[j].z - mx); v[j].w = __expf(v[j].w - mx);
        s += v[j].x + v[j].y + v[j].z + v[j].w;
    }
    #pragma unroll
    for (int o = 16; o > 0; o >>= 1) s += __shfl_xor_sync(0xffffffffu, s, o);
    if (lane == 0) ssum[warp] = s;
    __syncthreads();
    s = 0.f;
    #pragma unroll
    for (int w = 0; w < 8; w++) s += ssum[w];

    float inv = 1.f / s;
    #pragma unroll
    for (int j = 0; j < 4; j++) {
        v[j].x *= inv; v[j].y *= inv; v[j].z *= inv; v[j].w *= inv;
        *(float4*)&base[(j * 256 + tid) * 4] = v[j];
    }
}

// ---------------- zero ctx accumulator ----------------
__global__ void zero_ctx_kernel()
{
    int i = blockIdx.x * blockDim.x + threadIdx.x;
    if (i < BATCH * HEADS * CH * CH) g_ctxT[i] = 0.f;
}

// =======================================================================
// ctx via tf32 MMA: ctxT[e][d] = sum_n v[e,n]*k[d,n]
// per (bh, K-split): M=N=96, K=512. 8 warps = 2(M) x 4(N), warp 48x24.
// A = v rows (m x k row-major), B = k rows (n x k row-major -> col-major) — ok.
// =======================================================================
__global__ __launch_bounds__(256)
void ctx_tf32_kernel()
{
    int sk = blockIdx.x;                  // 0..CTX_SPLIT-1
    int bh = blockIdx.y;                  // 0..63
    int b = bh >> 2, h = bh & 3;
    const float* kb = g_qkv + ((size_t)b * QKVROWS + DIMC     + h * CH) * NPIX;
    const float* vb = g_qkv + ((size_t)b * QKVROWS + 2 * DIMC + h * CH) * NPIX;

    __shared__ float As[BK][CH + 4];      // v tile: [n_local][e]
    __shared__ float Bs[BK][CH + 4];      // k tile: [n_local][d]

    int tid  = threadIdx.x;
    int lane = tid & 31;
    int wid  = tid >> 5;
    int warpM = wid & 1;                  // 0..1 -> 48-row slices (e)
    int warpN = wid >> 1;                 // 0..3 -> 24-col slices (d)
    int gid = lane >> 2;
    int tig = lane & 3;

    float acc[3][3][4];
    #pragma unroll
    for (int i = 0; i < 3; i++)
        #pragma unroll
        for (int j = 0; j < 3; j++)
            #pragma unroll
            for (int t = 0; t < 4; t++) acc[i][j][t] = 0.f;

    const int KLEN = NPIX / CTX_SPLIT;    // 512
    int n0 = sk * KLEN;

    for (int nt = 0; nt < KLEN; nt += BK) {
        // load v,k tiles: 96 rows x 16 n-cols each = 384 float4 per matrix
        #pragma unroll
        for (int i = 0; i < 2; i++) {
            int idx = tid + i * 256;
            if (idx < 384) {
                int r  = idx >> 2;        // 0..95
                int c4 = (idx & 3) << 2;  // 0,4,8,12
                float4 a = *(const float4*)&vb[(size_t)r * NPIX + n0 + nt + c4];
                As[c4 + 0][r] = f2tf(a.x); As[c4 + 1][r] = f2tf(a.y);
                As[c4 + 2][r] = f2tf(a.z); As[c4 + 3][r] = f2tf(a.w);
                float4 bq = *(const float4*)&kb[(size_t)r * NPIX + n0 + nt + c4];
                Bs[c4 + 0][r] = f2tf(bq.x); Bs[c4 + 1][r] = f2tf(bq.y);
                Bs[c4 + 2][r] = f2tf(bq.z); Bs[c4 + 3][r] = f2tf(bq.w);
            }
        }
        __syncthreads();

        #pragma unroll
        for (int ks = 0; ks < 2; ks++) {
            int kb8 = ks * 8;
            unsigned af[3][4];
            #pragma unroll
            for (int i = 0; i < 3; i++) {
                int mr = warpM * 48 + i * 16 + gid;
                af[i][0] = __float_as_uint(As[kb8 + tig    ][mr]);
                af[i][1] = __float_as_uint(As[kb8 + tig    ][mr + 8]);
                af[i][2] = __float_as_uint(As[kb8 + tig + 4][mr]);
                af[i][3] = __float_as_uint(As[kb8 + tig + 4][mr + 8]);
            }
            unsigned bf[3][2];
            #pragma unroll
            for (int j = 0; j < 3; j++) {
                int nc = warpN * 24 + j * 8 + gid;
                bf[j][0] = __float_as_uint(Bs[kb8 + tig    ][nc]);
                bf[j][1] = __float_as_uint(Bs[kb8 + tig + 4][nc]);
            }
            #pragma unroll
            for (int i = 0; i < 3; i++)
                #pragma unroll
                for (int j = 0; j < 3; j++) {
                    asm volatile(
                        "mma.sync.aligned.m16n8k8.row.col.f32.tf32.tf32.f32 "
                        "{%0,%1,%2,%3},{%4,%5,%6,%7},{%8,%9},{%0,%1,%2,%3};\n"
                        : "+f"(acc[i][j][0]), "+f"(acc[i][j][1]),
                          "+f"(acc[i][j][2]), "+f"(acc[i][j][3])
                        : "r"(af[i][0]), "r"(af[i][1]), "r"(af[i][2]), "r"(af[i][3]),
                          "r"(bf[j][0]), "r"(bf[j][1]));
                }
        }
        __syncthreads();
    }

    float* cb = g_ctxT + (size_t)bh * CH * CH;
    #pragma unroll
    for (int i = 0; i < 3; i++) {
        int e0 = warpM * 48 + i * 16 + gid;
        int e1 = e0 + 8;
        #pragma unroll
        for (int j = 0; j < 3; j++) {
            int d0 = warpN * 24 + j * 8 + 2 * tig;
            atomicAdd(&cb[e0 * CH + d0    ], acc[i][j][0]);
            atomicAdd(&cb[e0 * CH + d0 + 1], acc[i][j][1]);
            atomicAdd(&cb[e1 * CH + d0    ], acc[i][j][2]);
            atomicAdd(&cb[e1 * CH + d0 + 1], acc[i][j][3]);
        }
    }
}

// ---------------- final: LN(y)*outg + (x-mean)*rstd*preg ----------------
__global__ void final_kernel(const float* __restrict__ x, const float* __restrict__ preg,
                             const float* __restrict__ outg, float* __restrict__ out)
{
    size_t i = (size_t)blockIdx.x * blockDim.x + threadIdx.x;
    if (i >= (size_t)BATCH * DIMC * NPIX) return;
    int pix = (int)(i & 4095);
    int bc  = (int)(i >> 12);
    int c   = bc % DIMC;
    int b   = bc / DIMC;
    int bp  = b * NPIX + pix;
    float xn = (x[i]   - g_mean[bp])  * g_rstd[bp]  * preg[c];
    float yn = (g_y[i] - g_mean2[bp]) * g_rstd2[bp] * outg[c];
    out[i] = yn + xn;
}

// ---------------- launch ----------------
extern "C" void kernel_launch(void* const* d_in, const int* in_sizes, int n_in,
                              void* d_out, int out_size)
{
    const float* x    = (const float*)d_in[0];
    const float* preg = (const float*)d_in[1];
    const float* Wqkv = (const float*)d_in[2];
    const float* Wout = (const float*)d_in[3];
    const float* bout = (const float*)d_in[4];
    const float* outg = (const float*)d_in[5];
    float* out = (float*)d_out;
    (void)in_sizes; (void)n_in; (void)out_size;

    // 1. prep folded (tf32-rounded) weights + prenorm stats
    prep_w_kernel<<<(QKVROWS * 32 + 255) / 256, 256>>>(Wqkv, preg);
    chan_stats_kernel<0><<<(BATCH * NPIX) / 256, 256>>>(x);

    // 2. QKV GEMM (tf32, pipelined) with LN folded into epilogue
    tf32gemm_kernel<0, QKVROWS, DIMC><<<dim3(NPIX / BN, QKVROWS / BM, BATCH), 256>>>(nullptr, x, nullptr);

    // 3. softmaxes (in place in g_qkv)
    q_softmax_kernel<<<(BATCH * HEADS * NPIX) / 128, 128>>>();
    k_softmax_kernel<<<BATCH * DIMC, 256>>>();

    // 4. context (tf32 MMA, split-K via atomics) and apply to q (tf32 MMA)
    zero_ctx_kernel<<<(BATCH * HEADS * CH * CH + 255) / 256, 256>>>();
    ctx_tf32_kernel<<<dim3(CTX_SPLIT, BATCH * HEADS), 256>>>();
    tf32gemm_kernel<2, CH, CH><<<dim3(NPIX / BN, 1, BATCH * HEADS), 256>>>(nullptr, nullptr, nullptr);

    // 5. out projection + bias (tf32, pipelined)
    tf32gemm_kernel<1, DIMC, DIMC><<<dim3(NPIX / BN, DIMC / BM, BATCH), 256>>>(Wout, nullptr, bout);

    // 6. out-LN stats + fused LN/residual epilogue
    chan_stats_kernel<1><<<(BATCH * NPIX) / 256, 256>>>(nullptr);
    final_kernel<<<(int)(((size_t)BATCH * DIMC * NPIX + 255) / 256), 256>>>(x, preg, outg, out);
}

// round 6
// speedup vs baseline: 2.7248x; 1.2532x over previous
#include <cuda_runtime.h>
#include <cuda_fp16.h>
#include <math.h>

// ---------------- problem constants ----------------
#define DIMC   384
#define NPIX   4096
#define BATCH  16
#define HEADS  4
#define CH     96
#define QKVROWS 1152
#define QSCALE 0.1020620726159658f   // 96^-0.5
#define CTX_SPLIT 8

// ---------------- scratch (device globals; allocation-free contract) ----------------
__device__ float g_Wg[QKVROWS * DIMC];
__device__ float g_wsum[QKVROWS];
__device__ float g_mean[BATCH * NPIX];
__device__ float g_rstd[BATCH * NPIX];
__device__ float g_mean2[BATCH * NPIX];
__device__ float g_rstd2[BATCH * NPIX];
__device__ float g_qkv[(size_t)BATCH * QKVROWS * NPIX];     // 302 MB
__device__ float g_ctxT[BATCH * HEADS * CH * CH];           // ctx^T: [bh][e][d]
__device__ float g_attn[(size_t)BATCH * DIMC * NPIX];       // 100 MB
__device__ float g_y[(size_t)BATCH * DIMC * NPIX];          // 100 MB

// ---------------- helpers ----------------
__device__ __forceinline__ unsigned f2tf_u(float f) {
    unsigned u;
    asm("cvt.rna.tf32.f32 %0, %1;" : "=r"(u) : "f"(f));
    return u;
}
__device__ __forceinline__ float f2tf(float f) {
    return __uint_as_float(f2tf_u(f));
}

// ---------------- prep: W' = fp16-rounded(Wqkv * prenorm_g), row sums ----------------
// Round through fp16 so the GEMM's half-converted weights match wsum exactly.
__global__ void prep_w_kernel(const float* __restrict__ W, const float* __restrict__ g)
{
    int warp = (blockIdx.x * blockDim.x + threadIdx.x) >> 5;
    int lane = threadIdx.x & 31;
    if (warp >= QKVROWS) return;
    float s = 0.f;
    for (int c = lane; c < DIMC; c += 32) {
        float w = __half2float(__float2half_rn(W[warp * DIMC + c] * g[c]));
        g_Wg[warp * DIMC + c] = w;
        s += w;
    }
    #pragma unroll
    for (int o = 16; o > 0; o >>= 1) s += __shfl_down_sync(0xffffffffu, s, o);
    if (lane == 0) g_wsum[warp] = s;
}

// ---------------- channel-LN statistics over C=384 ----------------
template<int MODE>
__global__ void chan_stats_kernel(const float* __restrict__ xarg)
{
    int p = blockIdx.x * blockDim.x + threadIdx.x;
    if (p >= BATCH * NPIX) return;
    const float* src = (MODE == 0) ? xarg : g_y;
    const float* base = src + (size_t)(p >> 12) * DIMC * NPIX + (p & (NPIX - 1));
    float s = 0.f, s2 = 0.f;
    #pragma unroll 4
    for (int c = 0; c < DIMC; c++) {
        float v = base[(size_t)c * NPIX];
        s += v; s2 += v * v;
    }
    float m   = s * (1.f / DIMC);
    float var = s2 * (1.f / DIMC) - m * m;
    float r   = rsqrtf(var + 1e-5f);
    if (MODE == 0) { g_mean[p]  = m; g_rstd[p]  = r; }
    else           { g_mean2[p] = m; g_rstd2[p] = r; }
}

// =======================================================================
// fp16 tensor-core GEMM (fp32 accum): 128x128x16, 256 thr (8 warps 4x2),
// warp tile 32x64, mma.sync.m16n8k16.row.col.f32.f16.f16.f32,
// register-staged software pipeline.
// KIND 0: qkv = rstd*(Wg@x - mean*wsum)     A=g_Wg      B=x(arg)   C=g_qkv
// KIND 1: y   = Wout@attn + bout            A=Wout(arg) B=g_attn   C=g_y
// KIND 2: attn= ctxT@q (per b,h; M=96,K=96) A=g_ctxT    B=q region C=g_attn
// =======================================================================
#define BM 128
#define BN 128
#define BK 16
#define PADH 4          // smem k-stride = BK+PADH = 20 halves (40B)

template<int KIND, int M, int K>
__global__ __launch_bounds__(256, 2)
void h16gemm_kernel(const float* __restrict__ Aext, const float* __restrict__ Bext,
                    const float* __restrict__ bias)
{
    const int N = NPIX;
    __shared__ __half As[BM][BK + PADH];   // [m][k]
    __shared__ __half Bs[BN][BK + PADH];   // [n][k]

    int z = blockIdx.z;
    const float* A; const float* B; float* C;
    const float* mean = nullptr; const float* rstd = nullptr;

    if (KIND == 0) {
        A = g_Wg;
        B = Bext + (size_t)z * K * N;
        C = g_qkv + (size_t)z * M * N;
        mean = g_mean + (size_t)z * N;
        rstd = g_rstd + (size_t)z * N;
    } else if (KIND == 1) {
        A = Aext;
        B = g_attn + (size_t)z * K * N;
        C = g_y + (size_t)z * M * N;
    } else { // KIND == 2: apply ctxT @ q
        int b = z >> 2, h = z & 3;
        A = g_ctxT + (size_t)z * CH * CH;
        B = g_qkv + ((size_t)b * QKVROWS + h * CH) * N;       // q region
        C = g_attn + ((size_t)b * DIMC + h * CH) * N;
    }

    int tid  = threadIdx.x;
    int lane = tid & 31;
    int wid  = tid >> 5;
    int warpM = wid & 3;        // 0..3 -> 32-row slices
    int warpN = wid >> 2;       // 0..1 -> 64-col slices
    int gid = lane >> 2;        // 0..7
    int tig = lane & 3;         // 0..3

    int rowBase = blockIdx.y * BM;
    int colBase = blockIdx.x * BN;

    // B column-load coords: 128 threads cover n, 2 groups cover k-halves
    int tn = tid & 127;
    int kg = tid >> 7;          // 0 or 1

    float acc[2][8][4];
    #pragma unroll
    for (int i = 0; i < 2; i++)
        #pragma unroll
        for (int j = 0; j < 8; j++)
            #pragma unroll
            for (int t = 0; t < 4; t++) acc[i][j][t] = 0.f;

    float4 aReg[2];
    float  bReg[8];

    // prologue: stage K-tile 0
    #pragma unroll
    for (int i = 0; i < 2; i++) {
        int idx = tid + i * 256;
        int r   = idx >> 2;
        int c4  = (idx & 3) << 2;
        int gr  = rowBase + r;
        aReg[i] = (gr < M) ? *(const float4*)&A[(size_t)gr * K + c4]
                           : make_float4(0.f, 0.f, 0.f, 0.f);
    }
    #pragma unroll
    for (int j = 0; j < 8; j++)
        bReg[j] = B[(size_t)(kg * 8 + j) * N + colBase + tn];

    for (int k0 = 0; k0 < K; k0 += BK) {
        // commit staged registers -> smem halves
        #pragma unroll
        for (int i = 0; i < 2; i++) {
            int idx = tid + i * 256;
            int r   = idx >> 2;
            int c4  = (idx & 3) << 2;
            *(half2*)&As[r][c4]     = __floats2half2_rn(aReg[i].x, aReg[i].y);
            *(half2*)&As[r][c4 + 2] = __floats2half2_rn(aReg[i].z, aReg[i].w);
        }
        #pragma unroll
        for (int j = 0; j < 4; j++)
            *(half2*)&Bs[tn][kg * 8 + 2 * j] = __floats2half2_rn(bReg[2 * j], bReg[2 * j + 1]);
        __syncthreads();

        // prefetch next K-tile (latency hidden under the MMAs below)
        int k1 = k0 + BK;
        if (k1 < K) {
            #pragma unroll
            for (int i = 0; i < 2; i++) {
                int idx = tid + i * 256;
                int r   = idx >> 2;
                int c4  = (idx & 3) << 2;
                int gr  = rowBase + r;
                aReg[i] = (gr < M) ? *(const float4*)&A[(size_t)gr * K + k1 + c4]
                                   : make_float4(0.f, 0.f, 0.f, 0.f);
            }
            #pragma unroll
            for (int j = 0; j < 8; j++)
                bReg[j] = B[(size_t)(k1 + kg * 8 + j) * N + colBase + tn];
        }

        // fragments + MMA (single k16 step per tile)
        unsigned af[2][4];
        #pragma unroll
        for (int i = 0; i < 2; i++) {
            int mr = warpM * 32 + i * 16 + gid;
            af[i][0] = *(const unsigned*)&As[mr    ][2 * tig];
            af[i][1] = *(const unsigned*)&As[mr + 8][2 * tig];
            af[i][2] = *(const unsigned*)&As[mr    ][2 * tig + 8];
            af[i][3] = *(const unsigned*)&As[mr + 8][2 * tig + 8];
        }
        unsigned bf[8][2];
        #pragma unroll
        for (int j = 0; j < 8; j++) {
            int nc = warpN * 64 + j * 8 + gid;
            bf[j][0] = *(const unsigned*)&Bs[nc][2 * tig];
            bf[j][1] = *(const unsigned*)&Bs[nc][2 * tig + 8];
        }
        #pragma unroll
        for (int i = 0; i < 2; i++)
            #pragma unroll
            for (int j = 0; j < 8; j++) {
                asm volatile(
                    "mma.sync.aligned.m16n8k16.row.col.f32.f16.f16.f32 "
                    "{%0,%1,%2,%3},{%4,%5,%6,%7},{%8,%9},{%0,%1,%2,%3};\n"
                    : "+f"(acc[i][j][0]), "+f"(acc[i][j][1]),
                      "+f"(acc[i][j][2]), "+f"(acc[i][j][3])
                    : "r"(af[i][0]), "r"(af[i][1]), "r"(af[i][2]), "r"(af[i][3]),
                      "r"(bf[j][0]), "r"(bf[j][1]));
            }
        __syncthreads();
    }

    // ---------------- epilogue (C fragment layout == tf32 case) ----------------
    #pragma unroll
    for (int i = 0; i < 2; i++) {
        int r0 = rowBase + warpM * 32 + i * 16 + gid;
        int r1 = r0 + 8;
        float w0 = 0.f, w1 = 0.f, bb0 = 0.f, bb1 = 0.f;
        if (KIND == 0)      { w0 = g_wsum[r0]; w1 = g_wsum[r1]; }
        else if (KIND == 1) { bb0 = bias[r0];  bb1 = bias[r1]; }
        #pragma unroll
        for (int j = 0; j < 8; j++) {
            int c0 = colBase + warpN * 64 + j * 8 + 2 * tig;
            if (KIND == 0) {
                float m0 = mean[c0], m1 = mean[c0 + 1];
                float v0 = rstd[c0], v1 = rstd[c0 + 1];
                float2 o0 = make_float2(v0 * (acc[i][j][0] - m0 * w0),
                                        v1 * (acc[i][j][1] - m1 * w0));
                float2 o1 = make_float2(v0 * (acc[i][j][2] - m0 * w1),
                                        v1 * (acc[i][j][3] - m1 * w1));
                *(float2*)&C[(size_t)r0 * N + c0] = o0;
                *(float2*)&C[(size_t)r1 * N + c0] = o1;
            } else if (KIND == 1) {
                float2 o0 = make_float2(acc[i][j][0] + bb0, acc[i][j][1] + bb0);
                float2 o1 = make_float2(acc[i][j][2] + bb1, acc[i][j][3] + bb1);
                *(float2*)&C[(size_t)r0 * N + c0] = o0;
                *(float2*)&C[(size_t)r1 * N + c0] = o1;
            } else {
                if (r0 < M)
                    *(float2*)&C[(size_t)r0 * N + c0] =
                        make_float2(acc[i][j][0], acc[i][j][1]);
                if (r1 < M)
                    *(float2*)&C[(size_t)r1 * N + c0] =
                        make_float2(acc[i][j][2], acc[i][j][3]);
            }
        }
    }
}

// ---------------- q softmax over channel dim (96) per (b,h,pixel) ----------------
__global__ __launch_bounds__(128) void q_softmax_kernel()
{
    int idx = blockIdx.x * blockDim.x + threadIdx.x;
    if (idx >= BATCH * HEADS * NPIX) return;
    int pix = idx & 4095;
    int h   = (idx >> 12) & 3;
    int b   = idx >> 14;
    float* base = g_qkv + ((size_t)b * QKVROWS + h * CH) * NPIX + pix;

    float v[CH];
    float mx = -1e30f;
    #pragma unroll
    for (int d = 0; d < CH; d++) {
        v[d] = base[(size_t)d * NPIX];
        mx = fmaxf(mx, v[d]);
    }
    float s = 0.f;
    #pragma unroll
    for (int d = 0; d < CH; d++) {
        v[d] = __expf(v[d] - mx);
        s += v[d];
    }
    float inv = QSCALE / s;
    #pragma unroll
    for (int d = 0; d < CH; d++) base[(size_t)d * NPIX] = v[d] * inv;
}

// ---------------- k softmax over spatial dim (4096) per (b, channel) ----------------
__global__ __launch_bounds__(256) void k_softmax_kernel()
{
    int row = blockIdx.x;
    int b = row / DIMC, r = row % DIMC;
    float* base = g_qkv + ((size_t)b * QKVROWS + DIMC + r) * NPIX;
    int tid  = threadIdx.x;
    int lane = tid & 31, warp = tid >> 5;

    float4 v[4];
    float mx = -1e30f;
    #pragma unroll
    for (int j = 0; j < 4; j++) {
        v[j] = *(const float4*)&base[(j * 256 + tid) * 4];
        mx = fmaxf(mx, fmaxf(fmaxf(v[j].x, v[j].y), fmaxf(v[j].z, v[j].w)));
    }
    __shared__ float smax[8];
    __shared__ float ssum[8];
    #pragma unroll
    for (int o = 16; o > 0; o >>= 1) mx = fmaxf(mx, __shfl_xor_sync(0xffffffffu, mx, o));
    if (lane == 0) smax[warp] = mx;
    __syncthreads();
    mx = smax[0];
    #pragma unroll
    for (int w = 1; w < 8; w++) mx = fmaxf(mx, smax[w]);

    float s = 0.f;
    #pragma unroll
    for (int j = 0; j < 4; j++) {
        v[j].x = __expf(v[j].x - mx); v[j].y = __expf(v[j].y - mx);
        v[j].z = __expf(v[j].z - mx); v[j].w = __expf(v[j].w - mx);
        s += v[j].x + v[j].y + v[j].z + v[j].w;
    }
    #pragma unroll
    for (int o = 16; o > 0; o >>= 1) s += __shfl_xor_sync(0xffffffffu, s, o);
    if (lane == 0) ssum[warp] = s;
    __syncthreads();
    s = 0.f;
    #pragma unroll
    for (int w = 0; w < 8; w++) s += ssum[w];

    float inv = 1.f / s;
    #pragma unroll
    for (int j = 0; j < 4; j++) {
        v[j].x *= inv; v[j].y *= inv; v[j].z *= inv; v[j].w *= inv;
        *(float4*)&base[(j * 256 + tid) * 4] = v[j];
    }
}

// ---------------- zero ctx accumulator ----------------
__global__ void zero_ctx_kernel()
{
    int i = blockIdx.x * blockDim.x + threadIdx.x;
    if (i < BATCH * HEADS * CH * CH) g_ctxT[i] = 0.f;
}

// =======================================================================
// ctx via tf32 MMA: ctxT[e][d] = sum_n v[e,n]*k[d,n]  (unchanged from R5)
// =======================================================================
__global__ __launch_bounds__(256)
void ctx_tf32_kernel()
{
    int sk = blockIdx.x;
    int bh = blockIdx.y;
    int b = bh >> 2, h = bh & 3;
    const float* kb = g_qkv + ((size_t)b * QKVROWS + DIMC     + h * CH) * NPIX;
    const float* vb = g_qkv + ((size_t)b * QKVROWS + 2 * DIMC + h * CH) * NPIX;

    __shared__ float As[BK][CH + 4];
    __shared__ float Bs[BK][CH + 4];

    int tid  = threadIdx.x;
    int lane = tid & 31;
    int wid  = tid >> 5;
    int warpM = wid & 1;
    int warpN = wid >> 1;
    int gid = lane >> 2;
    int tig = lane & 3;

    float acc[3][3][4];
    #pragma unroll
    for (int i = 0; i < 3; i++)
        #pragma unroll
        for (int j = 0; j < 3; j++)
            #pragma unroll
            for (int t = 0; t < 4; t++) acc[i][j][t] = 0.f;

    const int KLEN = NPIX / CTX_SPLIT;
    int n0 = sk * KLEN;

    for (int nt = 0; nt < KLEN; nt += BK) {
        #pragma unroll
        for (int i = 0; i < 2; i++) {
            int idx = tid + i * 256;
            if (idx < 384) {
                int r  = idx >> 2;
                int c4 = (idx & 3) << 2;
                float4 a = *(const float4*)&vb[(size_t)r * NPIX + n0 + nt + c4];
                As[c4 + 0][r] = f2tf(a.x); As[c4 + 1][r] = f2tf(a.y);
                As[c4 + 2][r] = f2tf(a.z); As[c4 + 3][r] = f2tf(a.w);
                float4 bq = *(const float4*)&kb[(size_t)r * NPIX + n0 + nt + c4];
                Bs[c4 + 0][r] = f2tf(bq.x); Bs[c4 + 1][r] = f2tf(bq.y);
                Bs[c4 + 2][r] = f2tf(bq.z); Bs[c4 + 3][r] = f2tf(bq.w);
            }
        }
        __syncthreads();

        #pragma unroll
        for (int ks = 0; ks < 2; ks++) {
            int kb8 = ks * 8;
            unsigned af[3][4];
            #pragma unroll
            for (int i = 0; i < 3; i++) {
                int mr = warpM * 48 + i * 16 + gid;
                af[i][0] = __float_as_uint(As[kb8 + tig    ][mr]);
                af[i][1] = __float_as_uint(As[kb8 + tig    ][mr + 8]);
                af[i][2] = __float_as_uint(As[kb8 + tig + 4][mr]);
                af[i][3] = __float_as_uint(As[kb8 + tig + 4][mr + 8]);
            }
            unsigned bf[3][2];
            #pragma unroll
            for (int j = 0; j < 3; j++) {
                int nc = warpN * 24 + j * 8 + gid;
                bf[j][0] = __float_as_uint(Bs[kb8 + tig    ][nc]);
                bf[j][1] = __float_as_uint(Bs[kb8 + tig + 4][nc]);
            }
            #pragma unroll
            for (int i = 0; i < 3; i++)
                #pragma unroll
                for (int j = 0; j < 3; j++) {
                    asm volatile(
                        "mma.sync.aligned.m16n8k8.row.col.f32.tf32.tf32.f32 "
                        "{%0,%1,%2,%3},{%4,%5,%6,%7},{%8,%9},{%0,%1,%2,%3};\n"
                        : "+f"(acc[i][j][0]), "+f"(acc[i][j][1]),
                          "+f"(acc[i][j][2]), "+f"(acc[i][j][3])
                        : "r"(af[i][0]), "r"(af[i][1]), "r"(af[i][2]), "r"(af[i][3]),
                          "r"(bf[j][0]), "r"(bf[j][1]));
                }
        }
        __syncthreads();
    }

    float* cb = g_ctxT + (size_t)bh * CH * CH;
    #pragma unroll
    for (int i = 0; i < 3; i++) {
        int e0 = warpM * 48 + i * 16 + gid;
        int e1 = e0 + 8;
        #pragma unroll
        for (int j = 0; j < 3; j++) {
            int d0 = warpN * 24 + j * 8 + 2 * tig;
            atomicAdd(&cb[e0 * CH + d0    ], acc[i][j][0]);
            atomicAdd(&cb[e0 * CH + d0 + 1], acc[i][j][1]);
            atomicAdd(&cb[e1 * CH + d0    ], acc[i][j][2]);
            atomicAdd(&cb[e1 * CH + d0 + 1], acc[i][j][3]);
        }
    }
}

// ---------------- final: LN(y)*outg + (x-mean)*rstd*preg ----------------
__global__ void final_kernel(const float* __restrict__ x, const float* __restrict__ preg,
                             const float* __restrict__ outg, float* __restrict__ out)
{
    size_t i = (size_t)blockIdx.x * blockDim.x + threadIdx.x;
    if (i >= (size_t)BATCH * DIMC * NPIX) return;
    int pix = (int)(i & 4095);
    int bc  = (int)(i >> 12);
    int c   = bc % DIMC;
    int b   = bc / DIMC;
    int bp  = b * NPIX + pix;
    float xn = (x[i]   - g_mean[bp])  * g_rstd[bp]  * preg[c];
    float yn = (g_y[i] - g_mean2[bp]) * g_rstd2[bp] * outg[c];
    out[i] = yn + xn;
}

// ---------------- launch ----------------
extern "C" void kernel_launch(void* const* d_in, const int* in_sizes, int n_in,
                              void* d_out, int out_size)
{
    const float* x    = (const float*)d_in[0];
    const float* preg = (const float*)d_in[1];
    const float* Wqkv = (const float*)d_in[2];
    const float* Wout = (const float*)d_in[3];
    const float* bout = (const float*)d_in[4];
    const float* outg = (const float*)d_in[5];
    float* out = (float*)d_out;
    (void)in_sizes; (void)n_in; (void)out_size;

    // 1. prep folded (fp16-rounded) weights + prenorm stats
    prep_w_kernel<<<(QKVROWS * 32 + 255) / 256, 256>>>(Wqkv, preg);
    chan_stats_kernel<0><<<(BATCH * NPIX) / 256, 256>>>(x);

    // 2. QKV GEMM (fp16 MMA, pipelined) with LN folded into epilogue
    h16gemm_kernel<0, QKVROWS, DIMC><<<dim3(NPIX / BN, QKVROWS / BM, BATCH), 256>>>(nullptr, x, nullptr);

    // 3. softmaxes (in place in g_qkv)
    q_softmax_kernel<<<(BATCH * HEADS * NPIX) / 128, 128>>>();
    k_softmax_kernel<<<BATCH * DIMC, 256>>>();

    // 4. context (tf32 MMA, split-K via atomics) and apply to q (fp16 MMA)
    zero_ctx_kernel<<<(BATCH * HEADS * CH * CH + 255) / 256, 256>>>();
    ctx_tf32_kernel<<<dim3(CTX_SPLIT, BATCH * HEADS), 256>>>();
    h16gemm_kernel<2, CH, CH><<<dim3(NPIX / BN, 1, BATCH * HEADS), 256>>>(nullptr, nullptr, nullptr);

    // 5. out projection + bias (fp16 MMA, pipelined)
    h16gemm_kernel<1, DIMC, DIMC><<<dim3(NPIX / BN, DIMC / BM, BATCH), 256>>>(Wout, nullptr, bout);

    // 6. out-LN stats + fused LN/residual epilogue
    chan_stats_kernel<1><<<(BATCH * NPIX) / 256, 256>>>(nullptr);
    final_kernel<<<(int)(((size_t)BATCH * DIMC * NPIX + 255) / 256), 256>>>(x, preg, outg, out);
}